// round 9
// baseline (speedup 1.0000x reference)
#include <cuda_runtime.h>
#include <cuda_bf16.h>
#include <cstdint>

#define N_PTS  4096
#define M_PTS  16384
#define C_IN   256
#define C_SKIP 128
#define C_CAT  384
#define H_DIM  256

// Scratch (device globals — no runtime allocation allowed)
__device__ __align__(16) __nv_bfloat16 g_fh[M_PTS * C_CAT];  // feat hi
__device__ __align__(16) __nv_bfloat16 g_fl[M_PTS * C_CAT];  // feat lo
__device__ __align__(16) __nv_bfloat16 g_hh[M_PTS * H_DIM];  // hidden hi
__device__ __align__(16) __nv_bfloat16 g_hl[M_PTS * H_DIM];  // hidden lo
__device__ __align__(16) __nv_bfloat16 g_w1h[C_CAT * H_DIM], g_w1l[C_CAT * H_DIM];
__device__ __align__(16) __nv_bfloat16 g_w2h[H_DIM * H_DIM], g_w2l[H_DIM * H_DIM];
__device__ int   g_idx[M_PTS * 3];
__device__ float g_w[M_PTS * 4];

// ---------------------------------------------------------------------------
// Kernel 1: brute-force kNN (k=3). 8 threads per query, 32 queries per block.
// ---------------------------------------------------------------------------
#define KNN_TILE 1024
#define QPB 32
#define TPQ 8
__global__ void knn_kernel(const float* __restrict__ pos,
                           const float* __restrict__ pos_skip) {
    __shared__ float sx[KNN_TILE], sy[KNN_TILE], sz[KNN_TILE];
    __shared__ float pd[QPB][TPQ][3];
    __shared__ int   pi[QPB][TPQ][3];

    int qi = threadIdx.x / TPQ;
    int ts = threadIdx.x % TPQ;
    int m  = blockIdx.x * QPB + qi;

    float qx = pos_skip[3 * m + 0];
    float qy = pos_skip[3 * m + 1];
    float qz = pos_skip[3 * m + 2];

    float d0 = 1e30f, d1 = 1e30f, d2 = 1e30f;
    int   i0 = 0, i1 = 0, i2 = 0;

    for (int base = 0; base < N_PTS; base += KNN_TILE) {
        __syncthreads();
        for (int j = threadIdx.x; j < KNN_TILE; j += blockDim.x) {
            sx[j] = pos[3 * (base + j) + 0];
            sy[j] = pos[3 * (base + j) + 1];
            sz[j] = pos[3 * (base + j) + 2];
        }
        __syncthreads();
        #pragma unroll 8
        for (int j = ts; j < KNN_TILE; j += TPQ) {
            float dx = qx - sx[j];
            float dy = qy - sy[j];
            float dz = qz - sz[j];
            float d = fmaf(dx, dx, fmaf(dy, dy, dz * dz));
            int gi = base + j;
            if (d < d2) {
                if (d < d1) {
                    d2 = d1; i2 = i1;
                    if (d < d0) { d1 = d0; i1 = i0; d0 = d; i0 = gi; }
                    else        { d1 = d;  i1 = gi; }
                } else { d2 = d; i2 = gi; }
            }
        }
    }

    pd[qi][ts][0] = d0; pd[qi][ts][1] = d1; pd[qi][ts][2] = d2;
    pi[qi][ts][0] = i0; pi[qi][ts][1] = i1; pi[qi][ts][2] = i2;
    __syncthreads();

    if (ts == 0) {
        float b0 = 1e30f, b1 = 1e30f, b2 = 1e30f;
        int   j0 = 0, j1 = 0, j2 = 0;
        #pragma unroll
        for (int t = 0; t < TPQ; t++) {
            #pragma unroll
            for (int s = 0; s < 3; s++) {
                float d = pd[qi][t][s];
                int   gi = pi[qi][t][s];
                if (d < b2) {
                    if (d < b1) {
                        b2 = b1; j2 = j1;
                        if (d < b0) { b1 = b0; j1 = j0; b0 = d; j0 = gi; }
                        else        { b1 = d;  j1 = gi; }
                    } else { b2 = d; j2 = gi; }
                }
            }
        }
        float w0 = 1.f / fmaxf(b0, 1e-16f);
        float w1 = 1.f / fmaxf(b1, 1e-16f);
        float w2 = 1.f / fmaxf(b2, 1e-16f);
        g_idx[3 * m + 0] = j0;
        g_idx[3 * m + 1] = j1;
        g_idx[3 * m + 2] = j2;
        g_w[4 * m + 0] = w0;
        g_w[4 * m + 1] = w1;
        g_w[4 * m + 2] = w2;
        g_w[4 * m + 3] = 1.f / (w0 + w1 + w2);
    }
}

// ---------------------------------------------------------------------------
// Helpers
// ---------------------------------------------------------------------------
__device__ __forceinline__ void split2bf(float v, __nv_bfloat16& hi,
                                         __nv_bfloat16& lo) {
    hi = __float2bfloat16(v);
    lo = __float2bfloat16(v - __bfloat162float(hi));
}
__device__ __forceinline__ uint32_t pack2(__nv_bfloat16 a, __nv_bfloat16 b) {
    __nv_bfloat162 t(a, b);
    return *(uint32_t*)&t;
}

// ---------------------------------------------------------------------------
// Kernel 2: interpolate + concat -> split bf16 feat [M,384]. Warp per row.
// ---------------------------------------------------------------------------
__global__ void interp_kernel(const float* __restrict__ x,
                              const float* __restrict__ x_skip) {
    int warp = (blockIdx.x * blockDim.x + threadIdx.x) >> 5;
    int lane = threadIdx.x & 31;
    if (warp >= M_PTS) return;
    int m = warp;

    int i0 = g_idx[3 * m + 0];
    int i1 = g_idx[3 * m + 1];
    int i2 = g_idx[3 * m + 2];
    float w0 = g_w[4 * m + 0];
    float w1 = g_w[4 * m + 1];
    float w2 = g_w[4 * m + 2];
    float inv = g_w[4 * m + 3];
    w0 *= inv; w1 *= inv; w2 *= inv;

    const float2* x0 = (const float2*)(x + (size_t)i0 * C_IN);
    const float2* x1 = (const float2*)(x + (size_t)i1 * C_IN);
    const float2* x2 = (const float2*)(x + (size_t)i2 * C_IN);
    const float2* xs = (const float2*)(x_skip + (size_t)m * C_SKIP);
    uint32_t* fh = (uint32_t*)(g_fh + (size_t)m * C_CAT);
    uint32_t* fl = (uint32_t*)(g_fl + (size_t)m * C_CAT);

    #pragma unroll
    for (int p = lane; p < 192; p += 32) {
        float v0, v1;
        if (p < 128) {
            float2 a = x0[p], b = x1[p], d = x2[p];
            v0 = w0 * a.x + w1 * b.x + w2 * d.x;
            v1 = w0 * a.y + w1 * b.y + w2 * d.y;
        } else {
            float2 s = xs[p - 128];
            v0 = s.x; v1 = s.y;
        }
        __nv_bfloat16 h0, l0, h1, l1;
        split2bf(v0, h0, l0);
        split2bf(v1, h1, l1);
        fh[p] = pack2(h0, h1);
        fl[p] = pack2(l0, l1);
    }
}

// ---------------------------------------------------------------------------
// Kernel 2b: split weights W1, W2 into bf16 hi/lo
// ---------------------------------------------------------------------------
__global__ void split_w_kernel(const float* __restrict__ W1,
                               const float* __restrict__ W2) {
    int i = blockIdx.x * blockDim.x + threadIdx.x;
    const int NW1 = C_CAT * H_DIM;
    const int NW2 = H_DIM * H_DIM;
    if (i < NW1) {
        __nv_bfloat16 h, l;
        split2bf(W1[i], h, l);
        g_w1h[i] = h; g_w1l[i] = l;
    } else if (i < NW1 + NW2) {
        int j = i - NW1;
        __nv_bfloat16 h, l;
        split2bf(W2[j], h, l);
        g_w2h[j] = h; g_w2l[j] = l;
    }
}

// ---------------------------------------------------------------------------
// Tensor-core GEMM, 3-phase compensated bf16, cp.async 4-stage pipeline.
//   C[M,256] = relu?(A[M,K] @ B[K,256] + bias),  A/B given as (hi, lo) pairs.
//   Phase 0: Ah*Bh   Phase 1: Al*Bh   Phase 2: Ah*Bl   (sum = fp32-accurate)
// BM=128, BN=64, BK=16; 8 warps (4m x 2n), warp tile 32x32.
// ---------------------------------------------------------------------------
#define MMA_BF16(acc, a, b)                                                   \
    asm volatile(                                                             \
        "mma.sync.aligned.m16n8k16.row.col.f32.bf16.bf16.f32 "                \
        "{%0,%1,%2,%3},{%4,%5,%6,%7},{%8,%9},{%0,%1,%2,%3};"                  \
        : "+f"((acc)[0]), "+f"((acc)[1]), "+f"((acc)[2]), "+f"((acc)[3])      \
        : "r"((a)[0]), "r"((a)[1]), "r"((a)[2]), "r"((a)[3]),                 \
          "r"((b)[0]), "r"((b)[1]))

__device__ __forceinline__ void ldsm_x4(uint32_t* r, uint32_t addr) {
    asm volatile(
        "ldmatrix.sync.aligned.m8n8.x4.shared.b16 {%0,%1,%2,%3},[%4];"
        : "=r"(r[0]), "=r"(r[1]), "=r"(r[2]), "=r"(r[3]) : "r"(addr));
}
__device__ __forceinline__ void ldsm_x4_t(uint32_t* r, uint32_t addr) {
    asm volatile(
        "ldmatrix.sync.aligned.m8n8.x4.trans.shared.b16 {%0,%1,%2,%3},[%4];"
        : "=r"(r[0]), "=r"(r[1]), "=r"(r[2]), "=r"(r[3]) : "r"(addr));
}
__device__ __forceinline__ void cp_async16(uint32_t saddr, const void* g) {
    asm volatile("cp.async.cg.shared.global [%0], [%1], 16;\n"
                 :: "r"(saddr), "l"(g));
}
__device__ __forceinline__ void cp_commit() {
    asm volatile("cp.async.commit_group;\n");
}
template <int N>
__device__ __forceinline__ void cp_wait() {
    asm volatile("cp.async.wait_group %0;\n" :: "n"(N));
}

#define G_STAGES 4

template <int KDIM, bool RELU, bool SPLIT_OUT>
__global__ void __launch_bounds__(256, 3)
gemm_bf16_tc(const __nv_bfloat16* __restrict__ Ahg,
             const __nv_bfloat16* __restrict__ Alg,
             const __nv_bfloat16* __restrict__ Bhg,
             const __nv_bfloat16* __restrict__ Blg,
             const float* __restrict__ bias,
             float* __restrict__ C,
             __nv_bfloat16* __restrict__ Ch,
             __nv_bfloat16* __restrict__ Cl) {
    const int BM = 128, BN = 64, BK = 16;
    const int ASTR = 24;   // bf16/row (48B) — ldmatrix conflict-free (validated R6)
    const int BSTR = 72;   // bf16/row (144B)
    const int NCOL = 256;
    const int KS = KDIM / BK;         // k-stages per phase
    const int NSTAGE = 3 * KS;        // total pipeline stages

    __shared__ __align__(16) __nv_bfloat16 sA[G_STAGES][BM * ASTR];
    __shared__ __align__(16) __nv_bfloat16 sB[G_STAGES][BK * BSTR];

    int tid  = threadIdx.x;
    int lane = tid & 31;
    int w    = tid >> 5;
    int wm   = w & 3, wn = w >> 2;
    int g    = lane >> 2, tq = lane & 3;
    int row0 = blockIdx.x * BM;
    int col0 = blockIdx.y * BN;

    // cp.async chunk mapping: A 256 chunks (1/thread), B 128 chunks (tid<128)
    int aRowL = tid >> 1, aHalf = tid & 1;         // A: row, 8-elem half
    int bRowL = (tid & 127) >> 3, bC8 = tid & 7;   // B: k-row, 8-elem col grp

    float acc[2][4][4];
    #pragma unroll
    for (int mt = 0; mt < 2; mt++)
        #pragma unroll
        for (int nt = 0; nt < 4; nt++)
            #pragma unroll
            for (int i = 0; i < 4; i++) acc[mt][nt][i] = 0.f;

    uint32_t sAaddr = (uint32_t)__cvta_generic_to_shared(&sA[0][0]);
    uint32_t sBaddr = (uint32_t)__cvta_generic_to_shared(&sB[0][0]);
    const uint32_t A_STAGE_B = BM * ASTR * 2;
    const uint32_t B_STAGE_B = BK * BSTR * 2;

    auto issue_stage = [&](int s) {
        int p  = s / KS;               // phase 0,1,2
        int k0 = (s - p * KS) * BK;
        const __nv_bfloat16* Aop = (p == 1) ? Alg : Ahg;
        const __nv_bfloat16* Bop = (p == 2) ? Blg : Bhg;
        int buf = s & (G_STAGES - 1);
        cp_async16(sAaddr + buf * A_STAGE_B + (aRowL * ASTR + 8 * aHalf) * 2,
                   Aop + (size_t)(row0 + aRowL) * KDIM + k0 + 8 * aHalf);
        if (tid < 128)
            cp_async16(sBaddr + buf * B_STAGE_B + (bRowL * BSTR + 8 * bC8) * 2,
                       Bop + (size_t)(k0 + bRowL) * NCOL + col0 + 8 * bC8);
        cp_commit();
    };

    // ldmatrix lane addressing (bytes, within a stage)
    int aOffB = (lane & 15) * ASTR * 2 + 16 * (lane >> 4);
    int bOffB = (lane & 15) * BSTR * 2 + (wn * 32 + 8 * (lane >> 4)) * 2;

    #pragma unroll
    for (int s = 0; s < G_STAGES - 1; s++) issue_stage(s);

    for (int s = 0; s < NSTAGE; s++) {
        cp_wait<G_STAGES - 2>();
        __syncthreads();

        if (s + G_STAGES - 1 < NSTAGE) issue_stage(s + G_STAGES - 1);

        int buf = s & (G_STAGES - 1);
        uint32_t baseA = sAaddr + buf * A_STAGE_B;
        uint32_t baseB = sBaddr + buf * B_STAGE_B;

        uint32_t a[2][4], b[4][2];
        #pragma unroll
        for (int mt = 0; mt < 2; mt++)
            ldsm_x4(a[mt], baseA + (wm * 32 + mt * 16) * ASTR * 2 + aOffB);
        #pragma unroll
        for (int p = 0; p < 2; p++) {
            uint32_t r[4];
            ldsm_x4_t(r, baseB + bOffB + p * 32);
            b[2 * p][0] = r[0]; b[2 * p][1] = r[1];
            b[2 * p + 1][0] = r[2]; b[2 * p + 1][1] = r[3];
        }

        #pragma unroll
        for (int mt = 0; mt < 2; mt++)
            #pragma unroll
            for (int nt = 0; nt < 4; nt++)
                MMA_BF16(acc[mt][nt], a[mt], b[nt]);

        __syncthreads();
    }

    // Epilogue
    #pragma unroll
    for (int mt = 0; mt < 2; mt++) {
        int r0 = row0 + wm * 32 + mt * 16 + g;
        #pragma unroll
        for (int nt = 0; nt < 4; nt++) {
            int c = col0 + wn * 32 + nt * 8 + 2 * tq;
            float bx = bias[c], by = bias[c + 1];
            float2 v0, v1;
            v0.x = acc[mt][nt][0] + bx;  v0.y = acc[mt][nt][1] + by;
            v1.x = acc[mt][nt][2] + bx;  v1.y = acc[mt][nt][3] + by;
            if (RELU) {
                v0.x = fmaxf(v0.x, 0.f); v0.y = fmaxf(v0.y, 0.f);
                v1.x = fmaxf(v1.x, 0.f); v1.y = fmaxf(v1.y, 0.f);
            }
            if (SPLIT_OUT) {
                __nv_bfloat16 h0, l0, h1, l1;
                split2bf(v0.x, h0, l0); split2bf(v0.y, h1, l1);
                *(uint32_t*)&Ch[(size_t)r0 * NCOL + c] = pack2(h0, h1);
                *(uint32_t*)&Cl[(size_t)r0 * NCOL + c] = pack2(l0, l1);
                split2bf(v1.x, h0, l0); split2bf(v1.y, h1, l1);
                *(uint32_t*)&Ch[(size_t)(r0 + 8) * NCOL + c] = pack2(h0, h1);
                *(uint32_t*)&Cl[(size_t)(r0 + 8) * NCOL + c] = pack2(l0, l1);
            } else {
                *(float2*)&C[(size_t)r0 * NCOL + c]       = v0;
                *(float2*)&C[(size_t)(r0 + 8) * NCOL + c] = v1;
            }
        }
    }
}

// ---------------------------------------------------------------------------
// Tail: copy pos_skip, zero the batch segment
// ---------------------------------------------------------------------------
__global__ void tail_kernel(const float* __restrict__ pos_skip,
                            float* __restrict__ out, int out_size) {
    const int base = M_PTS * H_DIM;
    for (int i = base + blockIdx.x * blockDim.x + threadIdx.x; i < out_size;
         i += gridDim.x * blockDim.x) {
        int r = i - base;
        out[i] = (r < M_PTS * 3) ? pos_skip[r] : 0.f;
    }
}

// ---------------------------------------------------------------------------
extern "C" void kernel_launch(void* const* d_in, const int* in_sizes, int n_in,
                              void* d_out, int out_size) {
    const float* x        = (const float*)d_in[0];
    const float* pos      = (const float*)d_in[1];
    const float* x_skip   = (const float*)d_in[3];
    const float* pos_skip = (const float*)d_in[4];
    const float* W1 = (const float*)d_in[6];
    const float* b1 = (const float*)d_in[7];
    const float* W2 = (const float*)d_in[8];
    const float* b2 = (const float*)d_in[9];
    float* out = (float*)d_out;

    split_w_kernel<<<(C_CAT * H_DIM + H_DIM * H_DIM + 255) / 256, 256>>>(W1, W2);
    knn_kernel<<<M_PTS / QPB, QPB * TPQ>>>(pos, pos_skip);
    interp_kernel<<<(M_PTS * 32) / 256, 256>>>(x, x_skip);

    __nv_bfloat16 *fh, *fl, *hh, *hl, *w1h, *w1l, *w2h, *w2l;
    cudaGetSymbolAddress((void**)&fh, g_fh);
    cudaGetSymbolAddress((void**)&fl, g_fl);
    cudaGetSymbolAddress((void**)&hh, g_hh);
    cudaGetSymbolAddress((void**)&hl, g_hl);
    cudaGetSymbolAddress((void**)&w1h, g_w1h);
    cudaGetSymbolAddress((void**)&w1l, g_w1l);
    cudaGetSymbolAddress((void**)&w2h, g_w2h);
    cudaGetSymbolAddress((void**)&w2l, g_w2l);

    dim3 grid(M_PTS / 128, H_DIM / 64);
    gemm_bf16_tc<C_CAT, true, true><<<grid, 256>>>(
        fh, fl, w1h, w1l, b1, nullptr, hh, hl);
    gemm_bf16_tc<H_DIM, false, false><<<grid, 256>>>(
        hh, hl, w2h, w2l, b2, out, nullptr, nullptr);

    tail_kernel<<<256, 256>>>(pos_skip, out, out_size);
}

// round 11
// speedup vs baseline: 1.1413x; 1.1413x over previous
#include <cuda_runtime.h>
#include <cuda_bf16.h>
#include <cstdint>

#define N_PTS  4096
#define M_PTS  16384
#define C_IN   256
#define C_SKIP 128
#define C_CAT  384
#define H_DIM  256

// Scratch (device globals — no runtime allocation allowed)
__device__ __align__(16) __nv_bfloat16 g_fh[M_PTS * C_CAT];  // feat hi
__device__ __align__(16) __nv_bfloat16 g_fl[M_PTS * C_CAT];  // feat lo
__device__ __align__(16) __nv_bfloat16 g_hh[M_PTS * H_DIM];  // hidden hi
__device__ __align__(16) __nv_bfloat16 g_hl[M_PTS * H_DIM];  // hidden lo
__device__ __align__(16) __nv_bfloat16 g_w1h[C_CAT * H_DIM], g_w1l[C_CAT * H_DIM];
__device__ __align__(16) __nv_bfloat16 g_w2h[H_DIM * H_DIM], g_w2l[H_DIM * H_DIM];
__device__ int   g_idx[M_PTS * 3];
__device__ float g_w[M_PTS * 4];

// ---------------------------------------------------------------------------
// Kernel 1: brute-force kNN (k=3). 8 threads per query, 32 queries per block.
// ---------------------------------------------------------------------------
#define KNN_TILE 1024
#define QPB 32
#define TPQ 8
__global__ void knn_kernel(const float* __restrict__ pos,
                           const float* __restrict__ pos_skip) {
    __shared__ float sx[KNN_TILE], sy[KNN_TILE], sz[KNN_TILE];
    __shared__ float pd[QPB][TPQ][3];
    __shared__ int   pi[QPB][TPQ][3];

    int qi = threadIdx.x / TPQ;
    int ts = threadIdx.x % TPQ;
    int m  = blockIdx.x * QPB + qi;

    float qx = pos_skip[3 * m + 0];
    float qy = pos_skip[3 * m + 1];
    float qz = pos_skip[3 * m + 2];

    float d0 = 1e30f, d1 = 1e30f, d2 = 1e30f;
    int   i0 = 0, i1 = 0, i2 = 0;

    for (int base = 0; base < N_PTS; base += KNN_TILE) {
        __syncthreads();
        for (int j = threadIdx.x; j < KNN_TILE; j += blockDim.x) {
            sx[j] = pos[3 * (base + j) + 0];
            sy[j] = pos[3 * (base + j) + 1];
            sz[j] = pos[3 * (base + j) + 2];
        }
        __syncthreads();
        #pragma unroll 8
        for (int j = ts; j < KNN_TILE; j += TPQ) {
            float dx = qx - sx[j];
            float dy = qy - sy[j];
            float dz = qz - sz[j];
            float d = fmaf(dx, dx, fmaf(dy, dy, dz * dz));
            int gi = base + j;
            if (d < d2) {
                if (d < d1) {
                    d2 = d1; i2 = i1;
                    if (d < d0) { d1 = d0; i1 = i0; d0 = d; i0 = gi; }
                    else        { d1 = d;  i1 = gi; }
                } else { d2 = d; i2 = gi; }
            }
        }
    }

    pd[qi][ts][0] = d0; pd[qi][ts][1] = d1; pd[qi][ts][2] = d2;
    pi[qi][ts][0] = i0; pi[qi][ts][1] = i1; pi[qi][ts][2] = i2;
    __syncthreads();

    if (ts == 0) {
        float b0 = 1e30f, b1 = 1e30f, b2 = 1e30f;
        int   j0 = 0, j1 = 0, j2 = 0;
        #pragma unroll
        for (int t = 0; t < TPQ; t++) {
            #pragma unroll
            for (int s = 0; s < 3; s++) {
                float d = pd[qi][t][s];
                int   gi = pi[qi][t][s];
                if (d < b2) {
                    if (d < b1) {
                        b2 = b1; j2 = j1;
                        if (d < b0) { b1 = b0; j1 = j0; b0 = d; j0 = gi; }
                        else        { b1 = d;  j1 = gi; }
                    } else { b2 = d; j2 = gi; }
                }
            }
        }
        float w0 = 1.f / fmaxf(b0, 1e-16f);
        float w1 = 1.f / fmaxf(b1, 1e-16f);
        float w2 = 1.f / fmaxf(b2, 1e-16f);
        g_idx[3 * m + 0] = j0;
        g_idx[3 * m + 1] = j1;
        g_idx[3 * m + 2] = j2;
        g_w[4 * m + 0] = w0;
        g_w[4 * m + 1] = w1;
        g_w[4 * m + 2] = w2;
        g_w[4 * m + 3] = 1.f / (w0 + w1 + w2);
    }
}

// ---------------------------------------------------------------------------
// Helpers
// ---------------------------------------------------------------------------
__device__ __forceinline__ void split2bf(float v, __nv_bfloat16& hi,
                                         __nv_bfloat16& lo) {
    hi = __float2bfloat16(v);
    lo = __float2bfloat16(v - __bfloat162float(hi));
}
__device__ __forceinline__ uint32_t pack2(__nv_bfloat16 a, __nv_bfloat16 b) {
    __nv_bfloat162 t(a, b);
    return *(uint32_t*)&t;
}

// ---------------------------------------------------------------------------
// Kernel 2: interpolate + concat -> split bf16 feat [M,384]. Warp per row.
// ---------------------------------------------------------------------------
__global__ void interp_kernel(const float* __restrict__ x,
                              const float* __restrict__ x_skip) {
    int warp = (blockIdx.x * blockDim.x + threadIdx.x) >> 5;
    int lane = threadIdx.x & 31;
    if (warp >= M_PTS) return;
    int m = warp;

    int i0 = g_idx[3 * m + 0];
    int i1 = g_idx[3 * m + 1];
    int i2 = g_idx[3 * m + 2];
    float w0 = g_w[4 * m + 0];
    float w1 = g_w[4 * m + 1];
    float w2 = g_w[4 * m + 2];
    float inv = g_w[4 * m + 3];
    w0 *= inv; w1 *= inv; w2 *= inv;

    const float2* x0 = (const float2*)(x + (size_t)i0 * C_IN);
    const float2* x1 = (const float2*)(x + (size_t)i1 * C_IN);
    const float2* x2 = (const float2*)(x + (size_t)i2 * C_IN);
    const float2* xs = (const float2*)(x_skip + (size_t)m * C_SKIP);
    uint32_t* fh = (uint32_t*)(g_fh + (size_t)m * C_CAT);
    uint32_t* fl = (uint32_t*)(g_fl + (size_t)m * C_CAT);

    #pragma unroll
    for (int p = lane; p < 192; p += 32) {
        float v0, v1;
        if (p < 128) {
            float2 a = x0[p], b = x1[p], d = x2[p];
            v0 = w0 * a.x + w1 * b.x + w2 * d.x;
            v1 = w0 * a.y + w1 * b.y + w2 * d.y;
        } else {
            float2 s = xs[p - 128];
            v0 = s.x; v1 = s.y;
        }
        __nv_bfloat16 h0, l0, h1, l1;
        split2bf(v0, h0, l0);
        split2bf(v1, h1, l1);
        fh[p] = pack2(h0, h1);
        fl[p] = pack2(l0, l1);
    }
}

// ---------------------------------------------------------------------------
// Kernel 2b: split weights W1, W2 into bf16 hi/lo
// ---------------------------------------------------------------------------
__global__ void split_w_kernel(const float* __restrict__ W1,
                               const float* __restrict__ W2) {
    int i = blockIdx.x * blockDim.x + threadIdx.x;
    const int NW1 = C_CAT * H_DIM;
    const int NW2 = H_DIM * H_DIM;
    if (i < NW1) {
        __nv_bfloat16 h, l;
        split2bf(W1[i], h, l);
        g_w1h[i] = h; g_w1l[i] = l;
    } else if (i < NW1 + NW2) {
        int j = i - NW1;
        __nv_bfloat16 h, l;
        split2bf(W2[j], h, l);
        g_w2h[j] = h; g_w2l[j] = l;
    }
}

// ---------------------------------------------------------------------------
// Tensor-core GEMM, 3-phase compensated bf16, BK=32, cp.async 3-stage ring,
// ONE __syncthreads per stage.
//   Phase 0: Ah*Bh   Phase 1: Al*Bh   Phase 2: Ah*Bl   (sum = fp32-accurate)
// BM=128, BN=64, BK=32; 8 warps (4m x 2n), warp tile 32x32; 16 MMA/stage.
// ---------------------------------------------------------------------------
#define MMA_BF16(acc, a, b)                                                   \
    asm volatile(                                                             \
        "mma.sync.aligned.m16n8k16.row.col.f32.bf16.bf16.f32 "                \
        "{%0,%1,%2,%3},{%4,%5,%6,%7},{%8,%9},{%0,%1,%2,%3};"                  \
        : "+f"((acc)[0]), "+f"((acc)[1]), "+f"((acc)[2]), "+f"((acc)[3])      \
        : "r"((a)[0]), "r"((a)[1]), "r"((a)[2]), "r"((a)[3]),                 \
          "r"((b)[0]), "r"((b)[1]))

__device__ __forceinline__ void ldsm_x4(uint32_t* r, uint32_t addr) {
    asm volatile(
        "ldmatrix.sync.aligned.m8n8.x4.shared.b16 {%0,%1,%2,%3},[%4];"
        : "=r"(r[0]), "=r"(r[1]), "=r"(r[2]), "=r"(r[3]) : "r"(addr));
}
__device__ __forceinline__ void ldsm_x4_t(uint32_t* r, uint32_t addr) {
    asm volatile(
        "ldmatrix.sync.aligned.m8n8.x4.trans.shared.b16 {%0,%1,%2,%3},[%4];"
        : "=r"(r[0]), "=r"(r[1]), "=r"(r[2]), "=r"(r[3]) : "r"(addr));
}
__device__ __forceinline__ void cp_async16(uint32_t saddr, const void* g) {
    asm volatile("cp.async.cg.shared.global [%0], [%1], 16;\n"
                 :: "r"(saddr), "l"(g));
}
__device__ __forceinline__ void cp_commit() {
    asm volatile("cp.async.commit_group;\n");
}
template <int N>
__device__ __forceinline__ void cp_wait() {
    asm volatile("cp.async.wait_group %0;\n" :: "n"(N));
}

#define G_STAGES 3

template <int KDIM, bool RELU, bool SPLIT_OUT>
__global__ void __launch_bounds__(256, 3)
gemm_bf16_tc(const __nv_bfloat16* __restrict__ Ahg,
             const __nv_bfloat16* __restrict__ Alg,
             const __nv_bfloat16* __restrict__ Bhg,
             const __nv_bfloat16* __restrict__ Blg,
             const float* __restrict__ bias,
             float* __restrict__ C,
             __nv_bfloat16* __restrict__ Ch,
             __nv_bfloat16* __restrict__ Cl) {
    const int BM = 128, BN = 64, BK = 32;
    const int ASTR = 40;   // bf16/row (80B) — banks (r*20)%32 all distinct
    const int BSTR = 72;   // bf16/row (144B) — banks (r*36)%32 all distinct
    const int NCOL = 256;
    const int KS = KDIM / BK;         // k-stages per phase
    const int NSTAGE = 3 * KS;        // total pipeline stages

    __shared__ __align__(16) __nv_bfloat16 sA[G_STAGES][BM * ASTR];  // 30720 B
    __shared__ __align__(16) __nv_bfloat16 sB[G_STAGES][BK * BSTR];  // 13824 B

    int tid  = threadIdx.x;
    int lane = tid & 31;
    int w    = tid >> 5;
    int wm   = w & 3, wn = w >> 2;
    int g    = lane >> 2, tq = lane & 3;
    int row0 = blockIdx.x * BM;
    int col0 = blockIdx.y * BN;

    // cp.async chunk maps. A: 512 chunks (2/thread): row=f>>2, k8=(f&3)*8.
    // B: 256 chunks (1/thread): k=f>>3, n8=(f&7)*8.
    int ar0 = tid >> 2,          ak0 = (tid & 3) * 8;
    int ar1 = (tid + 256) >> 2,  ak1 = (tid & 3) * 8;   // +256 keeps f&3
    int bk  = tid >> 3,          bn8 = (tid & 7) * 8;

    float acc[2][4][4];
    #pragma unroll
    for (int mt = 0; mt < 2; mt++)
        #pragma unroll
        for (int nt = 0; nt < 4; nt++)
            #pragma unroll
            for (int i = 0; i < 4; i++) acc[mt][nt][i] = 0.f;

    uint32_t sAaddr = (uint32_t)__cvta_generic_to_shared(&sA[0][0]);
    uint32_t sBaddr = (uint32_t)__cvta_generic_to_shared(&sB[0][0]);
    const uint32_t A_STAGE_B = BM * ASTR * 2;
    const uint32_t B_STAGE_B = BK * BSTR * 2;

    auto issue_stage = [&](int s, int buf) {
        const __nv_bfloat16* Aop = Ahg;
        const __nv_bfloat16* Bop = Bhg;
        int k0;
        if (s < KS)            { k0 = s * BK; }
        else if (s < 2 * KS)   { Aop = Alg; k0 = (s - KS) * BK; }
        else                   { Bop = Blg; k0 = (s - 2 * KS) * BK; }
        cp_async16(sAaddr + buf * A_STAGE_B + (ar0 * ASTR + ak0) * 2,
                   Aop + (size_t)(row0 + ar0) * KDIM + k0 + ak0);
        cp_async16(sAaddr + buf * A_STAGE_B + (ar1 * ASTR + ak1) * 2,
                   Aop + (size_t)(row0 + ar1) * KDIM + k0 + ak1);
        cp_async16(sBaddr + buf * B_STAGE_B + (bk * BSTR + bn8) * 2,
                   Bop + (size_t)(k0 + bk) * NCOL + col0 + bn8);
        cp_commit();
    };

    // ldmatrix lane addressing (bytes, within a stage)
    int aOffB = (lane & 15) * (ASTR * 2) + 16 * (lane >> 4);
    int bOffB = (lane & 15) * (BSTR * 2) + (wn * 32 + 8 * (lane >> 4)) * 2;

    issue_stage(0, 0);
    issue_stage(1, 1);

    int buf = 0, ibuf = 2;
    for (int s = 0; s < NSTAGE; s++) {
        cp_wait<G_STAGES - 2>();
        __syncthreads();    // all warps past stage s-1 reads -> ibuf reusable

        if (s + G_STAGES - 1 < NSTAGE) issue_stage(s + G_STAGES - 1, ibuf);

        uint32_t baseA = sAaddr + buf * A_STAGE_B;
        uint32_t baseB = sBaddr + buf * B_STAGE_B;

        #pragma unroll
        for (int ks = 0; ks < 2; ks++) {          // two k16 sub-tiles of BK=32
            uint32_t a[2][4], b[4][2];
            #pragma unroll
            for (int mt = 0; mt < 2; mt++)
                ldsm_x4(a[mt], baseA + (wm * 32 + mt * 16) * (ASTR * 2)
                                      + aOffB + ks * 32);
            #pragma unroll
            for (int p = 0; p < 2; p++) {
                uint32_t r[4];
                ldsm_x4_t(r, baseB + bOffB + p * 32 + ks * 16 * (BSTR * 2));
                b[2 * p][0] = r[0]; b[2 * p][1] = r[1];
                b[2 * p + 1][0] = r[2]; b[2 * p + 1][1] = r[3];
            }
            #pragma unroll
            for (int mt = 0; mt < 2; mt++)
                #pragma unroll
                for (int nt = 0; nt < 4; nt++)
                    MMA_BF16(acc[mt][nt], a[mt], b[nt]);
        }

        buf  = (buf == G_STAGES - 1) ? 0 : buf + 1;
        ibuf = (ibuf == G_STAGES - 1) ? 0 : ibuf + 1;
    }

    // Epilogue
    #pragma unroll
    for (int mt = 0; mt < 2; mt++) {
        int r0 = row0 + wm * 32 + mt * 16 + g;
        #pragma unroll
        for (int nt = 0; nt < 4; nt++) {
            int c = col0 + wn * 32 + nt * 8 + 2 * tq;
            float bx = bias[c], by = bias[c + 1];
            float2 v0, v1;
            v0.x = acc[mt][nt][0] + bx;  v0.y = acc[mt][nt][1] + by;
            v1.x = acc[mt][nt][2] + bx;  v1.y = acc[mt][nt][3] + by;
            if (RELU) {
                v0.x = fmaxf(v0.x, 0.f); v0.y = fmaxf(v0.y, 0.f);
                v1.x = fmaxf(v1.x, 0.f); v1.y = fmaxf(v1.y, 0.f);
            }
            if (SPLIT_OUT) {
                __nv_bfloat16 h0, l0, h1, l1;
                split2bf(v0.x, h0, l0); split2bf(v0.y, h1, l1);
                *(uint32_t*)&Ch[(size_t)r0 * NCOL + c] = pack2(h0, h1);
                *(uint32_t*)&Cl[(size_t)r0 * NCOL + c] = pack2(l0, l1);
                split2bf(v1.x, h0, l0); split2bf(v1.y, h1, l1);
                *(uint32_t*)&Ch[(size_t)(r0 + 8) * NCOL + c] = pack2(h0, h1);
                *(uint32_t*)&Cl[(size_t)(r0 + 8) * NCOL + c] = pack2(l0, l1);
            } else {
                *(float2*)&C[(size_t)r0 * NCOL + c]       = v0;
                *(float2*)&C[(size_t)(r0 + 8) * NCOL + c] = v1;
            }
        }
    }
}

// ---------------------------------------------------------------------------
// Tail: copy pos_skip, zero the batch segment
// ---------------------------------------------------------------------------
__global__ void tail_kernel(const float* __restrict__ pos_skip,
                            float* __restrict__ out, int out_size) {
    const int base = M_PTS * H_DIM;
    for (int i = base + blockIdx.x * blockDim.x + threadIdx.x; i < out_size;
         i += gridDim.x * blockDim.x) {
        int r = i - base;
        out[i] = (r < M_PTS * 3) ? pos_skip[r] : 0.f;
    }
}

// ---------------------------------------------------------------------------
extern "C" void kernel_launch(void* const* d_in, const int* in_sizes, int n_in,
                              void* d_out, int out_size) {
    const float* x        = (const float*)d_in[0];
    const float* pos      = (const float*)d_in[1];
    const float* x_skip   = (const float*)d_in[3];
    const float* pos_skip = (const float*)d_in[4];
    const float* W1 = (const float*)d_in[6];
    const float* b1 = (const float*)d_in[7];
    const float* W2 = (const float*)d_in[8];
    const float* b2 = (const float*)d_in[9];
    float* out = (float*)d_out;

    split_w_kernel<<<(C_CAT * H_DIM + H_DIM * H_DIM + 255) / 256, 256>>>(W1, W2);
    knn_kernel<<<M_PTS / QPB, QPB * TPQ>>>(pos, pos_skip);
    interp_kernel<<<(M_PTS * 32) / 256, 256>>>(x, x_skip);

    __nv_bfloat16 *fh, *fl, *hh, *hl, *w1h, *w1l, *w2h, *w2l;
    cudaGetSymbolAddress((void**)&fh, g_fh);
    cudaGetSymbolAddress((void**)&fl, g_fl);
    cudaGetSymbolAddress((void**)&hh, g_hh);
    cudaGetSymbolAddress((void**)&hl, g_hl);
    cudaGetSymbolAddress((void**)&w1h, g_w1h);
    cudaGetSymbolAddress((void**)&w1l, g_w1l);
    cudaGetSymbolAddress((void**)&w2h, g_w2h);
    cudaGetSymbolAddress((void**)&w2l, g_w2l);

    dim3 grid(M_PTS / 128, H_DIM / 64);
    gemm_bf16_tc<C_CAT, true, true><<<grid, 256>>>(
        fh, fl, w1h, w1l, b1, nullptr, hh, hl);
    gemm_bf16_tc<H_DIM, false, false><<<grid, 256>>>(
        hh, hl, w2h, w2l, b2, out, nullptr, nullptr);

    tail_kernel<<<256, 256>>>(pos_skip, out, out_size);
}

// round 14
// speedup vs baseline: 1.2874x; 1.1281x over previous
#include <cuda_runtime.h>
#include <cuda_bf16.h>
#include <cstdint>

#define N_PTS  4096
#define M_PTS  16384
#define C_IN   256
#define C_SKIP 128
#define C_CAT  384
#define H_DIM  256

// Scratch (device globals — no runtime allocation allowed)
__device__ __align__(16) __nv_bfloat16 g_fh[M_PTS * C_CAT];  // feat hi
__device__ __align__(16) __nv_bfloat16 g_fl[M_PTS * C_CAT];  // feat lo
__device__ __align__(16) __nv_bfloat16 g_hh[M_PTS * H_DIM];  // hidden hi
__device__ __align__(16) __nv_bfloat16 g_hl[M_PTS * H_DIM];  // hidden lo
__device__ __align__(16) __nv_bfloat16 g_w1h[C_CAT * H_DIM], g_w1l[C_CAT * H_DIM];
__device__ __align__(16) __nv_bfloat16 g_w2h[H_DIM * H_DIM], g_w2l[H_DIM * H_DIM];
__device__ int   g_idx[M_PTS * 3];
__device__ float g_w[M_PTS * 4];

// ---------------------------------------------------------------------------
// Kernel 1: brute-force kNN (k=3). 16 threads per query, 16 queries/block.
// ---------------------------------------------------------------------------
#define KNN_TILE 1024
#define QPB 16
#define TPQ 16
__global__ void knn_kernel(const float* __restrict__ pos,
                           const float* __restrict__ pos_skip) {
    __shared__ float sx[KNN_TILE], sy[KNN_TILE], sz[KNN_TILE];
    __shared__ float pd[QPB][TPQ][3];
    __shared__ int   pi[QPB][TPQ][3];

    int qi = threadIdx.x / TPQ;
    int ts = threadIdx.x % TPQ;
    int m  = blockIdx.x * QPB + qi;

    float qx = pos_skip[3 * m + 0];
    float qy = pos_skip[3 * m + 1];
    float qz = pos_skip[3 * m + 2];

    float d0 = 1e30f, d1 = 1e30f, d2 = 1e30f;
    int   i0 = 0, i1 = 0, i2 = 0;

    for (int base = 0; base < N_PTS; base += KNN_TILE) {
        __syncthreads();
        for (int j = threadIdx.x; j < KNN_TILE; j += blockDim.x) {
            sx[j] = pos[3 * (base + j) + 0];
            sy[j] = pos[3 * (base + j) + 1];
            sz[j] = pos[3 * (base + j) + 2];
        }
        __syncthreads();
        #pragma unroll 8
        for (int j = ts; j < KNN_TILE; j += TPQ) {
            float dx = qx - sx[j];
            float dy = qy - sy[j];
            float dz = qz - sz[j];
            float d = fmaf(dx, dx, fmaf(dy, dy, dz * dz));
            int gi = base + j;
            if (d < d2) {
                if (d < d1) {
                    d2 = d1; i2 = i1;
                    if (d < d0) { d1 = d0; i1 = i0; d0 = d; i0 = gi; }
                    else        { d1 = d;  i1 = gi; }
                } else { d2 = d; i2 = gi; }
            }
        }
    }

    pd[qi][ts][0] = d0; pd[qi][ts][1] = d1; pd[qi][ts][2] = d2;
    pi[qi][ts][0] = i0; pi[qi][ts][1] = i1; pi[qi][ts][2] = i2;
    __syncthreads();

    if (ts == 0) {
        float b0 = 1e30f, b1 = 1e30f, b2 = 1e30f;
        int   j0 = 0, j1 = 0, j2 = 0;
        #pragma unroll
        for (int t = 0; t < TPQ; t++) {
            #pragma unroll
            for (int s = 0; s < 3; s++) {
                float d = pd[qi][t][s];
                int   gi = pi[qi][t][s];
                if (d < b2) {
                    if (d < b1) {
                        b2 = b1; j2 = j1;
                        if (d < b0) { b1 = b0; j1 = j0; b0 = d; j0 = gi; }
                        else        { b1 = d;  j1 = gi; }
                    } else { b2 = d; j2 = gi; }
                }
            }
        }
        float w0 = 1.f / fmaxf(b0, 1e-16f);
        float w1 = 1.f / fmaxf(b1, 1e-16f);
        float w2 = 1.f / fmaxf(b2, 1e-16f);
        g_idx[3 * m + 0] = j0;
        g_idx[3 * m + 1] = j1;
        g_idx[3 * m + 2] = j2;
        g_w[4 * m + 0] = w0;
        g_w[4 * m + 1] = w1;
        g_w[4 * m + 2] = w2;
        g_w[4 * m + 3] = 1.f / (w0 + w1 + w2);
    }
}

// ---------------------------------------------------------------------------
// Helpers
// ---------------------------------------------------------------------------
__device__ __forceinline__ void split2bf(float v, __nv_bfloat16& hi,
                                         __nv_bfloat16& lo) {
    hi = __float2bfloat16(v);
    lo = __float2bfloat16(v - __bfloat162float(hi));
}
__device__ __forceinline__ uint32_t pack2(__nv_bfloat16 a, __nv_bfloat16 b) {
    __nv_bfloat162 t(a, b);
    return *(uint32_t*)&t;
}

// ---------------------------------------------------------------------------
// Kernel 2: interpolate + concat -> split bf16 feat [M,384]. Warp per row.
// ---------------------------------------------------------------------------
__global__ void interp_kernel(const float* __restrict__ x,
                              const float* __restrict__ x_skip) {
    int warp = (blockIdx.x * blockDim.x + threadIdx.x) >> 5;
    int lane = threadIdx.x & 31;
    if (warp >= M_PTS) return;
    int m = warp;

    int i0 = g_idx[3 * m + 0];
    int i1 = g_idx[3 * m + 1];
    int i2 = g_idx[3 * m + 2];
    float w0 = g_w[4 * m + 0];
    float w1 = g_w[4 * m + 1];
    float w2 = g_w[4 * m + 2];
    float inv = g_w[4 * m + 3];
    w0 *= inv; w1 *= inv; w2 *= inv;

    const float2* x0 = (const float2*)(x + (size_t)i0 * C_IN);
    const float2* x1 = (const float2*)(x + (size_t)i1 * C_IN);
    const float2* x2 = (const float2*)(x + (size_t)i2 * C_IN);
    const float2* xs = (const float2*)(x_skip + (size_t)m * C_SKIP);
    uint32_t* fh = (uint32_t*)(g_fh + (size_t)m * C_CAT);
    uint32_t* fl = (uint32_t*)(g_fl + (size_t)m * C_CAT);

    #pragma unroll
    for (int p = lane; p < 192; p += 32) {
        float v0, v1;
        if (p < 128) {
            float2 a = x0[p], b = x1[p], d = x2[p];
            v0 = w0 * a.x + w1 * b.x + w2 * d.x;
            v1 = w0 * a.y + w1 * b.y + w2 * d.y;
        } else {
            float2 s = xs[p - 128];
            v0 = s.x; v1 = s.y;
        }
        __nv_bfloat16 h0, l0, h1, l1;
        split2bf(v0, h0, l0);
        split2bf(v1, h1, l1);
        fh[p] = pack2(h0, h1);
        fl[p] = pack2(l0, l1);
    }
}

// ---------------------------------------------------------------------------
// Kernel 2b: split weights W1, W2 into bf16 hi/lo ([K][N] layout unchanged)
// ---------------------------------------------------------------------------
__global__ void split_w_kernel(const float* __restrict__ W1,
                               const float* __restrict__ W2) {
    int i = blockIdx.x * blockDim.x + threadIdx.x;
    const int NW1 = C_CAT * H_DIM;
    const int NW2 = H_DIM * H_DIM;
    if (i < NW1) {
        __nv_bfloat16 h, l;
        split2bf(W1[i], h, l);
        g_w1h[i] = h; g_w1l[i] = l;
    } else if (i < NW1 + NW2) {
        int j = i - NW1;
        __nv_bfloat16 h, l;
        split2bf(W2[j], h, l);
        g_w2h[j] = h; g_w2l[j] = l;
    }
}

// ---------------------------------------------------------------------------
// Tensor-core GEMM: fused 3-term compensated bf16.
// Per k16 stage: load Ah,Al,Bh,Bl tiles once; MMA AhBh + AlBh + AhBl (48 MMA).
// BM=128, BN=128, BK=16; 8 warps (4m x 2n), warp tile 32x64.
// Double-buffered cp.async. B smem uses XOR-chunk swizzle (no padding).
// ---------------------------------------------------------------------------
#define MMA_BF16(acc, a, b)                                                   \
    asm volatile(                                                             \
        "mma.sync.aligned.m16n8k16.row.col.f32.bf16.bf16.f32 "                \
        "{%0,%1,%2,%3},{%4,%5,%6,%7},{%8,%9},{%0,%1,%2,%3};"                  \
        : "+f"((acc)[0]), "+f"((acc)[1]), "+f"((acc)[2]), "+f"((acc)[3])      \
        : "r"((a)[0]), "r"((a)[1]), "r"((a)[2]), "r"((a)[3]),                 \
          "r"((b)[0]), "r"((b)[1]))

__device__ __forceinline__ void ldsm_x4(uint32_t* r, uint32_t addr) {
    asm volatile(
        "ldmatrix.sync.aligned.m8n8.x4.shared.b16 {%0,%1,%2,%3},[%4];"
        : "=r"(r[0]), "=r"(r[1]), "=r"(r[2]), "=r"(r[3]) : "r"(addr));
}
__device__ __forceinline__ void ldsm_x4_t(uint32_t* r, uint32_t addr) {
    asm volatile(
        "ldmatrix.sync.aligned.m8n8.x4.trans.shared.b16 {%0,%1,%2,%3},[%4];"
        : "=r"(r[0]), "=r"(r[1]), "=r"(r[2]), "=r"(r[3]) : "r"(addr));
}
__device__ __forceinline__ void cp_async16(uint32_t saddr, const void* g) {
    asm volatile("cp.async.cg.shared.global [%0], [%1], 16;\n"
                 :: "r"(saddr), "l"(g));
}
__device__ __forceinline__ void cp_commit() {
    asm volatile("cp.async.commit_group;\n");
}
template <int N>
__device__ __forceinline__ void cp_wait() {
    asm volatile("cp.async.wait_group %0;\n" :: "n"(N));
}

template <int KDIM, bool RELU, bool SPLIT_OUT>
__global__ void __launch_bounds__(256, 2)
gemm_bf16_tc(const __nv_bfloat16* __restrict__ Ahg,
             const __nv_bfloat16* __restrict__ Alg,
             const __nv_bfloat16* __restrict__ Bhg,
             const __nv_bfloat16* __restrict__ Blg,
             const float* __restrict__ bias,
             float* __restrict__ C,
             __nv_bfloat16* __restrict__ Ch,
             __nv_bfloat16* __restrict__ Cl) {
    const int BM = 128, BN = 128, BK = 16;
    const int ASTR = 24;          // bf16/row (48B), validated pad for ldsm A
    const int NCOL = 256;
    const int NSTAGE = KDIM / BK;

    __shared__ __align__(16) __nv_bfloat16 sAh[2][BM * ASTR];  // 6144 B each
    __shared__ __align__(16) __nv_bfloat16 sAl[2][BM * ASTR];
    __shared__ __align__(16) __nv_bfloat16 sBh[2][BK * BN];    // 4096 B each
    __shared__ __align__(16) __nv_bfloat16 sBl[2][BK * BN];

    int tid  = threadIdx.x;
    int lane = tid & 31;
    int w    = tid >> 5;
    int wm   = w & 3, wn = w >> 2;          // 4 m-warps x 2 n-warps
    int g    = lane >> 2, tq = lane & 3;
    int row0 = blockIdx.x * BM;
    int col0 = blockIdx.y * BN;

    // cp.async maps. A: 256 chunks (1/thread per array): row=tid>>1, half=tid&1
    int ar = tid >> 1, ah8 = (tid & 1) * 8;
    // B: 256 chunks (1/thread per array): k=tid>>4, chunk c=tid&15, XOR-swizzled
    int bkr = tid >> 4, bc = tid & 15;
    int bcs = (bc ^ bkr) * 16;              // physical 16B offset in row

    float acc[2][8][4];
    #pragma unroll
    for (int mt = 0; mt < 2; mt++)
        #pragma unroll
        for (int nt = 0; nt < 8; nt++)
            #pragma unroll
            for (int i = 0; i < 4; i++) acc[mt][nt][i] = 0.f;

    uint32_t aHaddr = (uint32_t)__cvta_generic_to_shared(&sAh[0][0]);
    uint32_t aLaddr = (uint32_t)__cvta_generic_to_shared(&sAl[0][0]);
    uint32_t bHaddr = (uint32_t)__cvta_generic_to_shared(&sBh[0][0]);
    uint32_t bLaddr = (uint32_t)__cvta_generic_to_shared(&sBl[0][0]);
    const uint32_t A_STG = BM * ASTR * 2;   // 6144
    const uint32_t B_STG = BK * BN * 2;     // 4096

    auto issue_stage = [&](int s, int buf) {
        int k0 = s * BK;
        const __nv_bfloat16* asrcH = Ahg + (size_t)(row0 + ar) * KDIM + k0 + ah8;
        const __nv_bfloat16* asrcL = Alg + (size_t)(row0 + ar) * KDIM + k0 + ah8;
        uint32_t adst = (ar * ASTR) * 2 + ah8 * 2;
        cp_async16(aHaddr + buf * A_STG + adst, asrcH);
        cp_async16(aLaddr + buf * A_STG + adst, asrcL);
        const __nv_bfloat16* bsrcH = Bhg + (size_t)(k0 + bkr) * NCOL + col0 + bc * 8;
        const __nv_bfloat16* bsrcL = Blg + (size_t)(k0 + bkr) * NCOL + col0 + bc * 8;
        uint32_t bdst = bkr * 256 + bcs;
        cp_async16(bHaddr + buf * B_STG + bdst, bsrcH);
        cp_async16(bLaddr + buf * B_STG + bdst, bsrcL);
        cp_commit();
    };

    // ldsm lane addressing
    int aOffB = (lane & 15) * (ASTR * 2) + 16 * (lane >> 4);
    int bRow  = lane & 15;                   // k-row for trans ldsm
    int bHgrp = lane >> 4;

    issue_stage(0, 0);

    for (int s = 0; s < NSTAGE; s++) {
        int buf = s & 1;
        if (s + 1 < NSTAGE) { issue_stage(s + 1, buf ^ 1); cp_wait<1>(); }
        else                { cp_wait<0>(); }
        __syncthreads();

        uint32_t baseAh = aHaddr + buf * A_STG;
        uint32_t baseAl = aLaddr + buf * A_STG;
        uint32_t baseBh = bHaddr + buf * B_STG;
        uint32_t baseBl = bLaddr + buf * B_STG;

        uint32_t a_h[2][4], a_l[2][4], b[8][2];
        #pragma unroll
        for (int mt = 0; mt < 2; mt++) {
            uint32_t off = (wm * 32 + mt * 16) * (ASTR * 2) + aOffB;
            ldsm_x4(a_h[mt], baseAh + off);
            ldsm_x4(a_l[mt], baseAl + off);
        }
        // Bh fragments: 4 trans ldsm cover nt pairs (2p, 2p+1)
        #pragma unroll
        for (int p = 0; p < 4; p++) {
            int clog = wn * 8 + 2 * p + bHgrp;
            uint32_t addr = baseBh + bRow * 256 + ((clog ^ bRow) << 4);
            uint32_t r[4];
            ldsm_x4_t(r, addr);
            b[2 * p][0] = r[0]; b[2 * p][1] = r[1];
            b[2 * p + 1][0] = r[2]; b[2 * p + 1][1] = r[3];
        }
        #pragma unroll
        for (int mt = 0; mt < 2; mt++)
            #pragma unroll
            for (int nt = 0; nt < 8; nt++) {
                MMA_BF16(acc[mt][nt], a_h[mt], b[nt]);   // Ah*Bh
                MMA_BF16(acc[mt][nt], a_l[mt], b[nt]);   // Al*Bh
            }
        // Bl fragments (reuse b regs)
        #pragma unroll
        for (int p = 0; p < 4; p++) {
            int clog = wn * 8 + 2 * p + bHgrp;
            uint32_t addr = baseBl + bRow * 256 + ((clog ^ bRow) << 4);
            uint32_t r[4];
            ldsm_x4_t(r, addr);
            b[2 * p][0] = r[0]; b[2 * p][1] = r[1];
            b[2 * p + 1][0] = r[2]; b[2 * p + 1][1] = r[3];
        }
        #pragma unroll
        for (int mt = 0; mt < 2; mt++)
            #pragma unroll
            for (int nt = 0; nt < 8; nt++)
                MMA_BF16(acc[mt][nt], a_h[mt], b[nt]);   // Ah*Bl

        __syncthreads();
    }

    // Epilogue
    #pragma unroll
    for (int mt = 0; mt < 2; mt++) {
        int r0 = row0 + wm * 32 + mt * 16 + g;
        #pragma unroll
        for (int nt = 0; nt < 8; nt++) {
            int c = col0 + wn * 64 + nt * 8 + 2 * tq;
            float bx = bias[c], by = bias[c + 1];
            float2 v0, v1;
            v0.x = acc[mt][nt][0] + bx;  v0.y = acc[mt][nt][1] + by;
            v1.x = acc[mt][nt][2] + bx;  v1.y = acc[mt][nt][3] + by;
            if (RELU) {
                v0.x = fmaxf(v0.x, 0.f); v0.y = fmaxf(v0.y, 0.f);
                v1.x = fmaxf(v1.x, 0.f); v1.y = fmaxf(v1.y, 0.f);
            }
            if (SPLIT_OUT) {
                __nv_bfloat16 h0, l0, h1, l1;
                split2bf(v0.x, h0, l0); split2bf(v0.y, h1, l1);
                *(uint32_t*)&Ch[(size_t)r0 * NCOL + c] = pack2(h0, h1);
                *(uint32_t*)&Cl[(size_t)r0 * NCOL + c] = pack2(l0, l1);
                split2bf(v1.x, h0, l0); split2bf(v1.y, h1, l1);
                *(uint32_t*)&Ch[(size_t)(r0 + 8) * NCOL + c] = pack2(h0, h1);
                *(uint32_t*)&Cl[(size_t)(r0 + 8) * NCOL + c] = pack2(l0, l1);
            } else {
                *(float2*)&C[(size_t)r0 * NCOL + c]       = v0;
                *(float2*)&C[(size_t)(r0 + 8) * NCOL + c] = v1;
            }
        }
    }
}

// ---------------------------------------------------------------------------
// Tail: copy pos_skip, zero the batch segment
// ---------------------------------------------------------------------------
__global__ void tail_kernel(const float* __restrict__ pos_skip,
                            float* __restrict__ out, int out_size) {
    const int base = M_PTS * H_DIM;
    for (int i = base + blockIdx.x * blockDim.x + threadIdx.x; i < out_size;
         i += gridDim.x * blockDim.x) {
        int r = i - base;
        out[i] = (r < M_PTS * 3) ? pos_skip[r] : 0.f;
    }
}

// ---------------------------------------------------------------------------
extern "C" void kernel_launch(void* const* d_in, const int* in_sizes, int n_in,
                              void* d_out, int out_size) {
    const float* x        = (const float*)d_in[0];
    const float* pos      = (const float*)d_in[1];
    const float* x_skip   = (const float*)d_in[3];
    const float* pos_skip = (const float*)d_in[4];
    const float* W1 = (const float*)d_in[6];
    const float* b1 = (const float*)d_in[7];
    const float* W2 = (const float*)d_in[8];
    const float* b2 = (const float*)d_in[9];
    float* out = (float*)d_out;

    split_w_kernel<<<(C_CAT * H_DIM + H_DIM * H_DIM + 255) / 256, 256>>>(W1, W2);
    knn_kernel<<<M_PTS / QPB, QPB * TPQ>>>(pos, pos_skip);
    interp_kernel<<<(M_PTS * 32) / 256, 256>>>(x, x_skip);

    __nv_bfloat16 *fh, *fl, *hh, *hl, *w1h, *w1l, *w2h, *w2l;
    cudaGetSymbolAddress((void**)&fh, g_fh);
    cudaGetSymbolAddress((void**)&fl, g_fl);
    cudaGetSymbolAddress((void**)&hh, g_hh);
    cudaGetSymbolAddress((void**)&hl, g_hl);
    cudaGetSymbolAddress((void**)&w1h, g_w1h);
    cudaGetSymbolAddress((void**)&w1l, g_w1l);
    cudaGetSymbolAddress((void**)&w2h, g_w2h);
    cudaGetSymbolAddress((void**)&w2l, g_w2l);

    dim3 grid(M_PTS / 128, H_DIM / 128);
    gemm_bf16_tc<C_CAT, true, true><<<grid, 256>>>(
        fh, fl, w1h, w1l, b1, nullptr, hh, hl);
    gemm_bf16_tc<H_DIM, false, false><<<grid, 256>>>(
        hh, hl, w2h, w2l, b2, out, nullptr, nullptr);

    tail_kernel<<<256, 256>>>(pos_skip, out, out_size);
}